// round 11
// baseline (speedup 1.0000x reference)
#include <cuda_runtime.h>

#define FULLMASK 0xFFFFFFFFu
#define KNN 16
#define GB 128                       // bins per axis
#define NB2 (GB * GB)                // 16384
#define XLO (-6.0f)
#define BINW (12.0f / 128.0f)
#define BSCALE (128.0f / 12.0f)
#define NCAP 32768
#define RBIG 3.0e38f
#define TPQ 8                        // threads per query

// ---- global scratch (no allocation; zero-initialized at module load) ----
// Self-cleaning: prefix_kernel re-zeros g_hist, knn8_kernel re-zeros g_cnt.
__device__ __align__(16) int g_hist[NB2];
__device__ __align__(16) int g_cnt[NB2];
__device__ __align__(16) int g_binstart[NB2 + 1];
__device__ __align__(16) float2 g_sxy[NCAP];
__device__ int g_sorig[NCAP];

static __device__ __forceinline__ int bin1(float v) {
    int b = (int)((v - XLO) * BSCALE);
    return min(max(b, 0), GB - 1);
}

// ================= setup kernels =================
__global__ void __launch_bounds__(1024, 1)
hist_kernel(const float* __restrict__ p, int n) {
    int i = blockIdx.x * blockDim.x + threadIdx.x;
    if (i < n) {
        float x = p[3 * i];
        float y = p[3 * i + 1];
        atomicAdd(&g_hist[(bin1(y) << 7) | bin1(x)], 1);
    }
}

// exclusive prefix over 16384 bins: 1024 threads x 16 bins each; re-zeros hist
__global__ void __launch_bounds__(1024, 1)
prefix_kernel() {
    __shared__ int wsum[32];
    const int tid = threadIdx.x;
    const int lane = tid & 31;
    const int wid = tid >> 5;
    int4* h4 = reinterpret_cast<int4*>(g_hist);

    int s = 0;
#pragma unroll
    for (int j = 0; j < 4; j++) {
        int4 v = h4[tid * 4 + j];
        s += v.x + v.y + v.z + v.w;
    }
    int x = s;
#pragma unroll
    for (int d = 1; d < 32; d <<= 1) {
        int y = __shfl_up_sync(FULLMASK, x, d);
        if (lane >= d) x += y;
    }
    if (lane == 31) wsum[wid] = x;
    __syncthreads();
    if (tid < 32) {
        int w = wsum[tid];
#pragma unroll
        for (int d = 1; d < 32; d <<= 1) {
            int y = __shfl_up_sync(FULLMASK, w, d);
            if (tid >= d) w += y;
        }
        wsum[tid] = w;
    }
    __syncthreads();
    int run = x - s + (wid ? wsum[wid - 1] : 0);
    const int4 z4 = make_int4(0, 0, 0, 0);
#pragma unroll
    for (int j = 0; j < 4; j++) {
        int4 v = h4[tid * 4 + j];
        int4 o;
        o.x = run;
        o.y = run + v.x;
        o.z = run + v.x + v.y;
        o.w = run + v.x + v.y + v.z;
        reinterpret_cast<int4*>(g_binstart)[tid * 4 + j] = o;
        h4[tid * 4 + j] = z4;           // self-clean
        run += v.x + v.y + v.z + v.w;
    }
    if (tid == 1023) g_binstart[NB2] = run;
}

__global__ void __launch_bounds__(1024, 1)
scatter_kernel(const float* __restrict__ p, int n) {
    int i = blockIdx.x * blockDim.x + threadIdx.x;
    if (i < n) {
        float x = p[3 * i];
        float y = p[3 * i + 1];
        int key = (bin1(y) << 7) | bin1(x);
        int pos = g_binstart[key] + atomicAdd(&g_cnt[key], 1);
        g_sxy[pos] = make_float2(x, y);
        g_sorig[pos] = i;
    }
}

// ================= main kernel: EIGHT threads per query =================
__global__ void __launch_bounds__(128, 1)
knn8_kernel(float* __restrict__ out, int n) {
    const int t = blockIdx.x * blockDim.x + threadIdx.x;

    // self-clean g_cnt for next replay (4096 int4s; plenty of threads)
    if (t < NB2 / 4) reinterpret_cast<int4*>(g_cnt)[t] = make_int4(0, 0, 0, 0);

    const int s = t >> 3;          // query slot
    const int sub = t & 7;         // group member 0..7
    if (s >= n) return;
    const unsigned gmask = 0xFFu << (threadIdx.x & 24);

    const float2 q = __ldg(&g_sxy[s]);
    const float xq = q.x;
    const float yq = q.y;

    // ---- prime: window of 128 slots, 16 per thread (stride 8) ----
    const int W = min(max(s - 64, 0), n - 128);
    float kn[KNN];
#pragma unroll
    for (int j = 0; j < KNN; j++) {
        int c = W + 8 * j + sub;
        float2 v = __ldg(&g_sxy[c]);
        float dx = xq - v.x;
        float dy = yq - v.y;
        float d2 = fmaf(dx, dx, dy * dy);
        kn[j] = (c == s) ? RBIG : d2;
    }
    // full bitonic sort of 16 registers (static network)
#pragma unroll
    for (int k = 2; k <= 16; k <<= 1) {
#pragma unroll
        for (int j = k >> 1; j > 0; j >>= 1) {
#pragma unroll
            for (int i = 0; i < 16; i++) {
                int l = i ^ j;
                if (l > i) {
                    bool up = ((i & k) == 0);
                    float mn = fminf(kn[i], kn[l]);
                    float mx = fmaxf(kn[i], kn[l]);
                    kn[i] = up ? mn : mx;
                    kn[l] = up ? mx : mn;
                }
            }
        }
    }
    float kn15 = kn[KNN - 1];

#define TRY_INSERT(D2)                                                \
    if ((D2) < kn15) {                                                \
        float v = (D2);                                               \
        _Pragma("unroll")                                             \
        for (int i = 0; i < KNN; i++) {                               \
            float lo = fminf(kn[i], v);                               \
            v = fmaxf(kn[i], v);                                      \
            kn[i] = lo;                                               \
        }                                                             \
        kn15 = kn[KNN - 1];                                           \
    }

    // group threshold: min of the 8 per-thread 16th-best upper bounds
    float kng = fminf(kn15, __shfl_xor_sync(gmask, kn15, 1));
    kng = fminf(kng, __shfl_xor_sync(gmask, kng, 2));
    kng = fminf(kng, __shfl_xor_sync(gmask, kng, 4));
    float rad = sqrtf(kng) * 1.0001f;

    // group-partitioned span scan (stride 8), MLP=2; window [W, W+128) skipped
    auto scan_span = [&](int lo, int hi) {
        int c = lo + sub;
        for (; c + 8 < hi; c += 16) {
            float2 v0 = __ldg(&g_sxy[c]);
            float2 v1 = __ldg(&g_sxy[c + 8]);
            float dx0 = xq - v0.x, dy0 = yq - v0.y;
            float dx1 = xq - v1.x, dy1 = yq - v1.y;
            float d20 = fmaf(dx0, dx0, dy0 * dy0);
            float d21 = fmaf(dx1, dx1, dy1 * dy1);
            TRY_INSERT(d20);
            TRY_INSERT(d21);
        }
        if (c < hi) {
            float2 v = __ldg(&g_sxy[c]);
            float dx = xq - v.x, dy = yq - v.y;
            float d2 = fmaf(dx, dx, dy * dy);
            TRY_INSERT(d2);
        }
    };

    auto scan_row = [&](int iy) {
        int bxlo = bin1(xq - rad);
        int bxhi = bin1(xq + rad);
        int base = iy << 7;
        int lo = __ldg(&g_binstart[base + bxlo]);
        int hi = __ldg(&g_binstart[base + bxhi + 1]);
        scan_span(lo, min(hi, W));
        scan_span(max(lo, W + 128), hi);
        kng = fminf(kn15, __shfl_xor_sync(gmask, kn15, 1));
        kng = fminf(kng, __shfl_xor_sync(gmask, kng, 2));
        kng = fminf(kng, __shfl_xor_sync(gmask, kng, 4));
        rad = sqrtf(kng) * 1.0001f;
    };

    const int iyq = bin1(yq);
    scan_row(iyq);
    for (int tt = 1;; tt++) {
        bool any = false;
        int ru = iyq + tt;
        if (ru < GB && yq + rad > XLO + (float)ru * BINW) {
            scan_row(ru);
            any = true;
        }
        int rd = iyq - tt;
        if (rd >= 0 && yq - rad < XLO + (float)(rd + 1) * BINW) {
            scan_row(rd);
            any = true;
        }
        if (!any) break;
    }
#undef TRY_INSERT

    // ---- merge the group's 8 sorted lists into the union top-16 ----
#pragma unroll
    for (int step = 1; step <= 4; step <<= 1) {
        float m[KNN];
#pragma unroll
        for (int i = 0; i < KNN; i++) {
            float b = __shfl_xor_sync(gmask, kn[KNN - 1 - i], step);
            m[i] = fminf(kn[i], b);   // bitonic sequence of union's 16 smallest
        }
#pragma unroll
        for (int j = 8; j > 0; j >>= 1) {
#pragma unroll
            for (int i = 0; i < 16; i++) {
                if (!(i & j)) {
                    float mn = fminf(m[i], m[i | j]);
                    float mx = fmaxf(m[i], m[i | j]);
                    m[i] = mn;
                    m[i | j] = mx;
                }
            }
        }
#pragma unroll
        for (int i = 0; i < KNN; i++) kn[i] = m[i];
    }

    // ---- output (one writer per query): sorted distances to original row ----
    if (sub == 0) {
        const int orig = __ldg(&g_sorig[s]);
        float4* o = reinterpret_cast<float4*>(out + (size_t)orig * KNN);
        float4 r0, r1, r2, r3;
        r0.x = sqrtf(kn[0]);  r0.y = sqrtf(kn[1]);  r0.z = sqrtf(kn[2]);  r0.w = sqrtf(kn[3]);
        r1.x = sqrtf(kn[4]);  r1.y = sqrtf(kn[5]);  r1.z = sqrtf(kn[6]);  r1.w = sqrtf(kn[7]);
        r2.x = sqrtf(kn[8]);  r2.y = sqrtf(kn[9]);  r2.z = sqrtf(kn[10]); r2.w = sqrtf(kn[11]);
        r3.x = sqrtf(kn[12]); r3.y = sqrtf(kn[13]); r3.z = sqrtf(kn[14]); r3.w = sqrtf(kn[15]);
        o[0] = r0; o[1] = r1; o[2] = r2; o[3] = r3;
    }
}

extern "C" void kernel_launch(void* const* d_in, const int* in_sizes, int n_in,
                              void* d_out, int out_size) {
    const float* p = (const float*)d_in[0];
    float* out = (float*)d_out;
    int n = in_sizes[0] / 3;

    int nb = (n + 1023) / 1024;
    hist_kernel<<<nb, 1024>>>(p, n);
    prefix_kernel<<<1, 1024>>>();
    scatter_kernel<<<nb, 1024>>>(p, n);

    long long threads = (long long)TPQ * n;
    int blocks = (int)((threads + 127) / 128);
    knn8_kernel<<<blocks, 128>>>(out, n);
}